// round 5
// baseline (speedup 1.0000x reference)
#include <cuda_runtime.h>

#define CC   256
#define HH   180
#define WW   360
#define HWSZ (HH*WW)          // 64800
#define HP   (HH+2)           // 182
#define WP   (WW+2)           // 362
#define OO   (2*CC)           // 512

// Scratch (no cudaMalloc allowed)
__device__ float g_pad[CC*HP*WP];   // ~67.5 MB padded image
__device__ float g_vel[OO*HWSZ];    // ~133 MB velocity field

// ---------------- geo_cyclic_pad ----------------
__global__ void pad_kernel(const float* __restrict__ hf) {
    int idx = blockIdx.x * blockDim.x + threadIdx.x;
    if (idx >= CC*HP*WP) return;
    int px = idx % WP;
    int py = (idx / WP) % HP;
    int c  = idx / (WP*HP);
    int yy; bool roll = false;
    if (py == 0)           { yy = 0;      roll = true; }
    else if (py == HP-1)   { yy = HH-1;   roll = true; }
    else                   { yy = py - 1; }
    int xx = px - 1;
    if (xx < 0)   xx += WW;
    if (xx >= WW) xx -= WW;
    if (roll) { xx -= WW/2; if (xx < 0) xx += WW; }
    g_pad[idx] = hf[c*HWSZ + yy*WW + xx];
}

// ---------------- fp32 tiled GEMM: vel[o][p] = sum_c w[o][c]*hf[c][p] + b[o] ----------------
#define BM 128
#define BN 128
#define BK 16
__global__ __launch_bounds__(256) void gemm_kernel(const float* __restrict__ hf,
                                                   const float* __restrict__ wv,
                                                   const float* __restrict__ bv) {
    __shared__ float As[BK][BM];
    __shared__ float Bs[BK][BN + 4];
    int t  = threadIdx.x;
    int p0 = blockIdx.x * BN;
    int o0 = blockIdx.y * BM;
    int tx = t & 15, ty = t >> 4;
    float acc[8][8];
    #pragma unroll
    for (int i = 0; i < 8; i++)
        #pragma unroll
        for (int j = 0; j < 8; j++) acc[i][j] = 0.f;

    for (int k0 = 0; k0 < CC; k0 += BK) {
        #pragma unroll
        for (int i = 0; i < 8; i++) {       // A tile: 128x16
            int idx = t + i*256;
            int m = idx >> 4, k = idx & 15;
            As[k][m] = wv[(o0 + m)*CC + k0 + k];
        }
        #pragma unroll
        for (int i = 0; i < 8; i++) {       // B tile: 16x128
            int idx = t + i*256;
            int k = idx >> 7, n = idx & 127;
            int p = p0 + n;
            Bs[k][n] = (p < HWSZ) ? hf[(k0 + k)*HWSZ + p] : 0.f;
        }
        __syncthreads();
        #pragma unroll
        for (int k = 0; k < BK; k++) {
            float a[8], b[8];
            #pragma unroll
            for (int i = 0; i < 8; i++) a[i] = As[k][ty*8 + i];
            #pragma unroll
            for (int j = 0; j < 8; j++) b[j] = Bs[k][tx*8 + j];
            #pragma unroll
            for (int i = 0; i < 8; i++)
                #pragma unroll
                for (int j = 0; j < 8; j++) acc[i][j] += a[i] * b[j];
        }
        __syncthreads();
    }
    #pragma unroll
    for (int i = 0; i < 8; i++) {
        int o = o0 + ty*8 + i;
        float bb = bv[o];
        #pragma unroll
        for (int j = 0; j < 8; j++) {
            int p = p0 + tx*8 + j;
            if (p < HWSZ) g_vel[o*HWSZ + p] = acc[i][j] + bb;
        }
    }
}

// ---------------- transform + bicubic sample ----------------
__device__ __forceinline__ float cc1f(float x) {           // A = -0.75
    return (1.25f*x - 2.25f)*x*x + 1.0f;
}
__device__ __forceinline__ float cc2f(float x) {
    return ((-0.75f*x + 3.75f)*x - 6.0f)*x + 3.0f;
}

__global__ __launch_bounds__(256) void sample_kernel(const float* __restrict__ lat_grid,
                                                     const float* __restrict__ lon_grid,
                                                     const int*   __restrict__ dtp,
                                                     float* __restrict__ out) {
    int p = blockIdx.x * blockDim.x + threadIdx.x;
    if (p >= HWSZ) return;
    int c = blockIdx.y;

    // dt dtype is ambiguous (int vs float bits) — decode deterministically
    int iv = *dtp;
    float dtf = (iv >= -1000000 && iv <= 1000000) ? (float)iv : __int_as_float(iv);

    float u = g_vel[c*HWSZ + p];
    float v = g_vel[(c + CC)*HWSZ + p];
    float lat_p = lat_grid[p];
    float lon_p = lon_grid[p];
    float min_lat = lat_grid[0], max_lat = lat_grid[(HH-1)*WW];
    float min_lon = lon_grid[0], max_lon = lon_grid[WW-1];

    float lon_pr = -u * dtf, lat_pr = -v * dtf;
    float slp, clp; sincosf(lat_pr, &slp, &clp);
    float slo, clo; sincosf(lon_pr, &slo, &clo);
    float sP,  cP;  sincosf(lat_p,  &sP,  &cP);

    float sin_lat = slp*cP + clp*clo*sP;
    sin_lat = fminf(fmaxf(sin_lat, -1.0f + 1e-7f), 1.0f - 1e-7f);
    float lat_dep = asinf(sin_lat);

    float num = clp * slo;
    float den = clp*clo*cP - slp*sP;
    const float TWO_PI = 6.283185307179586f;
    float lon_dep = lon_p + atan2f(num, den) + TWO_PI;
    lon_dep = lon_dep - TWO_PI * floorf(lon_dep * (1.0f / TWO_PI));

    float gx = (2.0f*(lon_dep - min_lon)/(max_lon - min_lon) - 1.0f) * ((float)WW / (float)WP);
    float gy = (2.0f*(lat_dep - min_lat)/(max_lat - min_lat) - 1.0f) * ((float)HH / (float)HP);
    float g1 = gx + 1.0f;
    gx = g1 - 2.0f*floorf(g1*0.5f) - 1.0f;
    if (gy < -1.0f)     gy = -(2.0f + gy);
    else if (gy > 1.0f) gy = 2.0f - gy;

    float ix = (gx + 1.0f) * 0.5f * (float)(WP - 1);
    float iy = (gy + 1.0f) * 0.5f * (float)(HP - 1);
    float ix0f = floorf(ix), iy0f = floorf(iy);
    float tx = ix - ix0f, ty = iy - iy0f;
    int ix0 = (int)ix0f, iy0 = (int)iy0f;

    float wx0 = cc2f(tx + 1.0f), wx1 = cc1f(tx), wx2 = cc1f(1.0f - tx), wx3 = cc2f(2.0f - tx);
    float wy0 = cc2f(ty + 1.0f), wy1 = cc1f(ty), wy2 = cc1f(1.0f - ty), wy3 = cc2f(2.0f - ty);

    int x0 = min(max(ix0 - 1, 0), WP-1);
    int x1 = min(max(ix0    , 0), WP-1);
    int x2 = min(max(ix0 + 1, 0), WP-1);
    int x3 = min(max(ix0 + 2, 0), WP-1);

    const float* img = g_pad + c*HP*WP;
    float acc = 0.f;
    float wyv[4] = {wy0, wy1, wy2, wy3};
    #pragma unroll
    for (int i = 0; i < 4; i++) {
        int yi = min(max(iy0 + i - 1, 0), HP-1);
        const float* r = img + yi*WP;
        float row = wx0*r[x0] + wx1*r[x1] + wx2*r[x2] + wx3*r[x3];
        acc += wyv[i] * row;
    }
    out[c*HWSZ + p] = acc;
}

extern "C" void kernel_launch(void* const* d_in, const int* in_sizes, int n_in,
                              void* d_out, int out_size) {
    const float* hf   = (const float*)d_in[0];
    const float* latg = (const float*)d_in[1];
    const float* long_= (const float*)d_in[2];
    const float* wv   = (const float*)d_in[3];
    const float* bv   = (const float*)d_in[4];
    const int*   dtp  = (const int*)  d_in[5];
    float* out = (float*)d_out;

    pad_kernel<<<(CC*HP*WP + 255)/256, 256>>>(hf);

    dim3 gg((HWSZ + BN - 1)/BN, OO/BM);
    gemm_kernel<<<gg, 256>>>(hf, wv, bv);

    dim3 gs((HWSZ + 255)/256, CC);
    sample_kernel<<<gs, 256>>>(latg, long_, dtp, out);
}

// round 11
// speedup vs baseline: 1.4898x; 1.4898x over previous
#include <cuda_runtime.h>
#include <cuda_bf16.h>
#include <mma.h>
#include <cstdint>

using namespace nvcuda;

#define CC   256
#define HH   180
#define WW   360
#define HWSZ (HH*WW)          // 64800
#define HP   (HH+2)           // 182
#define WP   (WW+2)           // 362
#define OO   (2*CC)           // 512
#define PPAD 64896            // 507*128 pixel rows (padded)

// Scratch (no cudaMalloc allowed)
__device__ float g_pad[CC*HP*WP];            // padded image
__device__ float g_vel[OO*HWSZ];             // velocity field [o][p]
__device__ __nv_bfloat16 g_ahi[PPAD*CC];     // hidden transposed [p][c], hi part
__device__ __nv_bfloat16 g_alo[PPAD*CC];     // lo part
__device__ __nv_bfloat16 g_bhi[OO*CC];       // weights [o][c] hi
__device__ __nv_bfloat16 g_blo[OO*CC];       // weights lo

// ======================= geo_cyclic_pad =======================
__global__ void pad_kernel(const float* __restrict__ hf) {
    int idx = blockIdx.x * blockDim.x + threadIdx.x;
    if (idx >= CC*HP*WP) return;
    int px = idx % WP;
    int py = (idx / WP) % HP;
    int c  = idx / (WP*HP);
    int yy; bool roll = false;
    if (py == 0)           { yy = 0;      roll = true; }
    else if (py == HP-1)   { yy = HH-1;   roll = true; }
    else                   { yy = py - 1; }
    int xx = px - 1;
    if (xx < 0)   xx += WW;
    if (xx >= WW) xx -= WW;
    if (roll) { xx -= WW/2; if (xx < 0) xx += WW; }
    g_pad[idx] = hf[c*HWSZ + yy*WW + xx];
}

// ======================= convert: hf [C][P] fp32 -> [P][C] bf16 hi/lo =======================
// block (32,8); tile = 64 channels x 32 pixels
__global__ __launch_bounds__(256) void convert_hf(const float* __restrict__ hf) {
    __shared__ float tile[64][33];
    int p0 = blockIdx.x * 32;
    int c0 = blockIdx.y * 64;
    int tx = threadIdx.x, ty = threadIdx.y;
    #pragma unroll
    for (int i = 0; i < 8; i++) {
        int c = c0 + ty + i*8;
        int p = p0 + tx;
        tile[ty + i*8][tx] = (p < HWSZ) ? hf[(size_t)c*HWSZ + p] : 0.f;
    }
    __syncthreads();
    #pragma unroll
    for (int i = 0; i < 4; i++) {
        int pl = ty + i*8;
        int p  = p0 + pl;
        float v0 = tile[2*tx][pl];
        float v1 = tile[2*tx+1][pl];
        __nv_bfloat16 h0 = __float2bfloat16(v0);
        __nv_bfloat16 h1 = __float2bfloat16(v1);
        __nv_bfloat16 l0 = __float2bfloat16(v0 - __bfloat162float(h0));
        __nv_bfloat16 l1 = __float2bfloat16(v1 - __bfloat162float(h1));
        size_t o = (size_t)p*CC + c0 + 2*tx;
        *reinterpret_cast<__nv_bfloat162*>(g_ahi + o) = __nv_bfloat162(h0, h1);
        *reinterpret_cast<__nv_bfloat162*>(g_alo + o) = __nv_bfloat162(l0, l1);
    }
}

__global__ void convert_w(const float* __restrict__ wv) {
    int i = blockIdx.x * blockDim.x + threadIdx.x;
    if (i >= OO*CC) return;
    float v = wv[i];
    __nv_bfloat16 h = __float2bfloat16(v);
    g_bhi[i] = h;
    g_blo[i] = __float2bfloat16(v - __bfloat162float(h));
}

// ======================= HMMA (wmma) GEMM ========================================
// vel[o][p] = sum_c w[o][c]*hf[c][p] + b[o]
// A = w [o][c] row-major (g_bhi/g_blo), B = hf^T [p][c] -> wmma col_major (g_ahi/g_alo)
// CTA tile: M=128 (o) x N=128 (p), K chunks of 64. 8 warps = 4(M) x 2(N); warp 32x64.
// hi/lo split: acc += Ahi*Bhi + Alo*Bhi + Ahi*Blo (fp32 accumulate).
#define TLD   72                       // smem tile ld (elements), 144B rows (9x16B skew)
#define TILE_ELE (128*TLD)             // one tile: 9216 bf16
#define EPI_LD 132
#define SM_BYTES (4*TILE_ELE*2 > 128*EPI_LD*4 ? 4*TILE_ELE*2 : 128*EPI_LD*4)

__global__ __launch_bounds__(256) void gemm_hmma(const float* __restrict__ bv) {
    extern __shared__ char smraw[];
    __nv_bfloat16* sAhi = reinterpret_cast<__nv_bfloat16*>(smraw);
    __nv_bfloat16* sAlo = sAhi + TILE_ELE;
    __nv_bfloat16* sBhi = sAhi + 2*TILE_ELE;
    __nv_bfloat16* sBlo = sAhi + 3*TILE_ELE;
    float* sC = reinterpret_cast<float*>(smraw);

    int tid = threadIdx.x;
    int wid = tid >> 5;
    int wm = wid >> 1;        // 0..3 : M (o) slice of 32
    int wn = wid & 1;         // 0..1 : N (p) slice of 64
    int p0 = blockIdx.x * 128;
    int oB = blockIdx.y * 128;

    wmma::fragment<wmma::accumulator, 16,16,16, float> acc[2][4];
    #pragma unroll
    for (int m = 0; m < 2; m++)
        #pragma unroll
        for (int n = 0; n < 4; n++) wmma::fill_fragment(acc[m][n], 0.0f);

    for (int ch = 0; ch < 4; ch++) {
        int k0 = ch * 64;
        // stage tiles: A (o x k) 128x64 hi/lo, B (p x k) 128x64 hi/lo
        #pragma unroll
        for (int it = 0; it < 4; it++) {
            int i = tid + it*256;            // 0..1023
            int row = i >> 3, q = i & 7;     // row 0..127, q = uint4 within 64-elem row
            const uint4* gAh = reinterpret_cast<const uint4*>(g_bhi + (size_t)(oB+row)*CC + k0);
            const uint4* gAl = reinterpret_cast<const uint4*>(g_blo + (size_t)(oB+row)*CC + k0);
            const uint4* gBh = reinterpret_cast<const uint4*>(g_ahi + (size_t)(p0+row)*CC + k0);
            const uint4* gBl = reinterpret_cast<const uint4*>(g_alo + (size_t)(p0+row)*CC + k0);
            *reinterpret_cast<uint4*>(sAhi + row*TLD + q*8) = gAh[q];
            *reinterpret_cast<uint4*>(sAlo + row*TLD + q*8) = gAl[q];
            *reinterpret_cast<uint4*>(sBhi + row*TLD + q*8) = gBh[q];
            *reinterpret_cast<uint4*>(sBlo + row*TLD + q*8) = gBl[q];
        }
        __syncthreads();

        #pragma unroll
        for (int ks = 0; ks < 4; ks++) {
            wmma::fragment<wmma::matrix_a, 16,16,16, __nv_bfloat16, wmma::row_major> ah[2], al[2];
            #pragma unroll
            for (int m = 0; m < 2; m++) {
                const __nv_bfloat16* ap = sAhi + (wm*32 + m*16)*TLD + ks*16;
                wmma::load_matrix_sync(ah[m], ap, TLD);
                wmma::load_matrix_sync(al[m], ap + TILE_ELE, TLD);    // sAlo
            }
            #pragma unroll
            for (int n = 0; n < 4; n++) {
                wmma::fragment<wmma::matrix_b, 16,16,16, __nv_bfloat16, wmma::col_major> bh, bl;
                const __nv_bfloat16* bp = sBhi + (wn*64 + n*16)*TLD + ks*16;
                wmma::load_matrix_sync(bh, bp, TLD);
                wmma::load_matrix_sync(bl, bp + TILE_ELE, TLD);       // sBlo
                #pragma unroll
                for (int m = 0; m < 2; m++) {
                    wmma::mma_sync(acc[m][n], ah[m], bh, acc[m][n]);
                    wmma::mma_sync(acc[m][n], al[m], bh, acc[m][n]);
                    wmma::mma_sync(acc[m][n], ah[m], bl, acc[m][n]);
                }
            }
        }
        __syncthreads();
    }

    // Epilogue: frags -> smem -> bias add -> coalesced g_vel[o][p]
    #pragma unroll
    for (int m = 0; m < 2; m++)
        #pragma unroll
        for (int n = 0; n < 4; n++)
            wmma::store_matrix_sync(sC + (wm*32 + m*16)*EPI_LD + wn*64 + n*16,
                                    acc[m][n], EPI_LD, wmma::mem_row_major);
    __syncthreads();
    for (int i = tid; i < 128*128; i += 256) {
        int c = i & 127, r = i >> 7;
        int p = p0 + c;
        if (p < HWSZ) {
            int o = oB + r;
            g_vel[(size_t)o*HWSZ + p] = sC[r*EPI_LD + c] + bv[o];
        }
    }
}

// ======================= transform + bicubic sample =======================
__device__ __forceinline__ float cc1f(float x) {
    return (1.25f*x - 2.25f)*x*x + 1.0f;
}
__device__ __forceinline__ float cc2f(float x) {
    return ((-0.75f*x + 3.75f)*x - 6.0f)*x + 3.0f;
}

__global__ __launch_bounds__(256) void sample_kernel(const float* __restrict__ lat_grid,
                                                     const float* __restrict__ lon_grid,
                                                     const int*   __restrict__ dtp,
                                                     float* __restrict__ out) {
    int p = blockIdx.x * blockDim.x + threadIdx.x;
    if (p >= HWSZ) return;
    int c = blockIdx.y;

    int iv = *dtp;
    float dtf = (iv >= -1000000 && iv <= 1000000) ? (float)iv : __int_as_float(iv);

    float u = g_vel[c*HWSZ + p];
    float v = g_vel[(c + CC)*HWSZ + p];
    float lat_p = lat_grid[p];
    float lon_p = lon_grid[p];
    float min_lat = lat_grid[0], max_lat = lat_grid[(HH-1)*WW];
    float min_lon = lon_grid[0], max_lon = lon_grid[WW-1];

    float lon_pr = -u * dtf, lat_pr = -v * dtf;
    // Precise trig everywhere: MUFU __sincosf's ~4e-7 abs error in cos terms is
    // amplified ~1000x by asin near the poles and broke the 1e-3 gate (R10).
    float slp, clp; sincosf(lat_pr, &slp, &clp);
    float slo, clo; sincosf(lon_pr, &slo, &clo);
    float sP,  cP;  sincosf(lat_p,  &sP,  &cP);

    float sin_lat = slp*cP + clp*clo*sP;
    sin_lat = fminf(fmaxf(sin_lat, -1.0f + 1e-7f), 1.0f - 1e-7f);
    float lat_dep = asinf(sin_lat);

    float num = clp * slo;
    float den = clp*clo*cP - slp*sP;
    const float TWO_PI = 6.283185307179586f;
    float lon_dep = lon_p + atan2f(num, den) + TWO_PI;
    lon_dep = lon_dep - TWO_PI * floorf(lon_dep * (1.0f / TWO_PI));

    float gx = (2.0f*(lon_dep - min_lon)/(max_lon - min_lon) - 1.0f) * ((float)WW / (float)WP);
    float gy = (2.0f*(lat_dep - min_lat)/(max_lat - min_lat) - 1.0f) * ((float)HH / (float)HP);
    float g1 = gx + 1.0f;
    gx = g1 - 2.0f*floorf(g1*0.5f) - 1.0f;
    if (gy < -1.0f)     gy = -(2.0f + gy);
    else if (gy > 1.0f) gy = 2.0f - gy;

    float ix = (gx + 1.0f) * 0.5f * (float)(WP - 1);
    float iy = (gy + 1.0f) * 0.5f * (float)(HP - 1);
    float ix0f = floorf(ix), iy0f = floorf(iy);
    float tx = ix - ix0f, ty = iy - iy0f;
    int ix0 = (int)ix0f, iy0 = (int)iy0f;

    float wx0 = cc2f(tx + 1.0f), wx1 = cc1f(tx), wx2 = cc1f(1.0f - tx), wx3 = cc2f(2.0f - tx);
    float wy0 = cc2f(ty + 1.0f), wy1 = cc1f(ty), wy2 = cc1f(1.0f - ty), wy3 = cc2f(2.0f - ty);

    int x0 = min(max(ix0 - 1, 0), WP-1);
    int x1 = min(max(ix0    , 0), WP-1);
    int x2 = min(max(ix0 + 1, 0), WP-1);
    int x3 = min(max(ix0 + 2, 0), WP-1);

    const float* img = g_pad + c*HP*WP;
    float acc = 0.f;
    float wyv[4] = {wy0, wy1, wy2, wy3};
    #pragma unroll
    for (int i = 0; i < 4; i++) {
        int yi = min(max(iy0 + i - 1, 0), HP-1);
        const float* r = img + yi*WP;
        float rowv = wx0*r[x0] + wx1*r[x1] + wx2*r[x2] + wx3*r[x3];
        acc += wyv[i] * rowv;
    }
    out[c*HWSZ + p] = acc;
}

extern "C" void kernel_launch(void* const* d_in, const int* in_sizes, int n_in,
                              void* d_out, int out_size) {
    const float* hf   = (const float*)d_in[0];
    const float* latg = (const float*)d_in[1];
    const float* long_= (const float*)d_in[2];
    const float* wv   = (const float*)d_in[3];
    const float* bv   = (const float*)d_in[4];
    const int*   dtp  = (const int*)  d_in[5];
    float* out = (float*)d_out;

    cudaFuncSetAttribute(gemm_hmma, cudaFuncAttributeMaxDynamicSharedMemorySize, SM_BYTES);

    pad_kernel<<<(CC*HP*WP + 255)/256, 256>>>(hf);

    convert_hf<<<dim3(PPAD/32, CC/64), dim3(32,8)>>>(hf);
    convert_w<<<(OO*CC + 255)/256, 256>>>(wv);

    gemm_hmma<<<dim3(507, OO/128), 256, SM_BYTES>>>(bv);

    dim3 gs((HWSZ + 255)/256, CC);
    sample_kernel<<<gs, 256>>>(latg, long_, dtp, out);
}

// round 12
// speedup vs baseline: 1.6211x; 1.0881x over previous
#include <cuda_runtime.h>
#include <cuda_bf16.h>
#include <mma.h>
#include <cstdint>

using namespace nvcuda;

#define CC   256
#define HH   180
#define WW   360
#define HWSZ (HH*WW)          // 64800
#define HP   (HH+2)           // 182
#define WP   (WW+2)           // 362
#define OO   (2*CC)           // 512
#define PPAD 64896            // 507*128 pixel rows (padded)

// Scratch (no cudaMalloc allowed)
__device__ float g_pad[CC*HP*WP];            // padded image
__device__ float g_vel[OO*HWSZ];             // velocity field [o][p]
__device__ float2 g_psc[HWSZ];               // per-pixel {sin(lat_p), cos(lat_p)}
__device__ __nv_bfloat16 g_ahi[PPAD*CC];     // hidden transposed [p][c], hi part
__device__ __nv_bfloat16 g_alo[PPAD*CC];     // lo part
__device__ __nv_bfloat16 g_bhi[OO*CC];       // weights [o][c] hi
__device__ __nv_bfloat16 g_blo[OO*CC];       // weights lo

// ======================= geo_cyclic_pad =======================
__global__ void pad_kernel(const float* __restrict__ hf) {
    int idx = blockIdx.x * blockDim.x + threadIdx.x;
    if (idx >= CC*HP*WP) return;
    int px = idx % WP;
    int py = (idx / WP) % HP;
    int c  = idx / (WP*HP);
    int yy; bool roll = false;
    if (py == 0)           { yy = 0;      roll = true; }
    else if (py == HP-1)   { yy = HH-1;   roll = true; }
    else                   { yy = py - 1; }
    int xx = px - 1;
    if (xx < 0)   xx += WW;
    if (xx >= WW) xx -= WW;
    if (roll) { xx -= WW/2; if (xx < 0) xx += WW; }
    g_pad[idx] = hf[c*HWSZ + yy*WW + xx];
}

// ======================= per-pixel sincos(lat) precompute =======================
__global__ void psc_kernel(const float* __restrict__ lat_grid) {
    int p = blockIdx.x * blockDim.x + threadIdx.x;
    if (p >= HWSZ) return;
    float s, c;
    sincosf(lat_grid[p], &s, &c);
    g_psc[p] = make_float2(s, c);
}

// ======================= convert: hf [C][P] fp32 -> [P][C] bf16 hi/lo =======================
__global__ __launch_bounds__(256) void convert_hf(const float* __restrict__ hf) {
    __shared__ float tile[64][33];
    int p0 = blockIdx.x * 32;
    int c0 = blockIdx.y * 64;
    int tx = threadIdx.x, ty = threadIdx.y;
    #pragma unroll
    for (int i = 0; i < 8; i++) {
        int c = c0 + ty + i*8;
        int p = p0 + tx;
        tile[ty + i*8][tx] = (p < HWSZ) ? hf[(size_t)c*HWSZ + p] : 0.f;
    }
    __syncthreads();
    #pragma unroll
    for (int i = 0; i < 4; i++) {
        int pl = ty + i*8;
        int p  = p0 + pl;
        float v0 = tile[2*tx][pl];
        float v1 = tile[2*tx+1][pl];
        __nv_bfloat16 h0 = __float2bfloat16(v0);
        __nv_bfloat16 h1 = __float2bfloat16(v1);
        __nv_bfloat16 l0 = __float2bfloat16(v0 - __bfloat162float(h0));
        __nv_bfloat16 l1 = __float2bfloat16(v1 - __bfloat162float(h1));
        size_t o = (size_t)p*CC + c0 + 2*tx;
        *reinterpret_cast<__nv_bfloat162*>(g_ahi + o) = __nv_bfloat162(h0, h1);
        *reinterpret_cast<__nv_bfloat162*>(g_alo + o) = __nv_bfloat162(l0, l1);
    }
}

__global__ void convert_w(const float* __restrict__ wv) {
    int i = blockIdx.x * blockDim.x + threadIdx.x;
    if (i >= OO*CC) return;
    float v = wv[i];
    __nv_bfloat16 h = __float2bfloat16(v);
    g_bhi[i] = h;
    g_blo[i] = __float2bfloat16(v - __bfloat162float(h));
}

// ======================= HMMA (wmma) GEMM, 2-stage cp.async pipeline ================
// vel[o][p] = sum_c w[o][c]*hf[c][p] + b[o]
// A = w [o][c] row-major (g_bhi/g_blo), B = hf^T [p][c] -> wmma col_major (g_ahi/g_alo)
// CTA tile: M=128 (o) x N=128 (p), K chunks of 64. 8 warps = 4(M) x 2(N).
// hi/lo split: acc += Ahi*Bhi + Alo*Bhi + Ahi*Blo (fp32 accumulate).
#define TLD   72                       // smem tile ld (elements), 144B rows
#define TILE_ELE (128*TLD)             // 9216 bf16 per tile
#define STAGE_ELE (4*TILE_ELE)         // Ahi,Alo,Bhi,Blo
#define EPI_LD 132
#define SM_BYTES (2*STAGE_ELE*2)       // 147456 B (epilogue 128*EPI_LD*4=67584 fits inside)

__device__ __forceinline__ void cpasync16(void* smem_dst, const void* gsrc) {
    uint32_t d = (uint32_t)__cvta_generic_to_shared(smem_dst);
    asm volatile("cp.async.cg.shared.global [%0], [%1], 16;" :: "r"(d), "l"(gsrc));
}

__global__ __launch_bounds__(256) void gemm_hmma(const float* __restrict__ bv) {
    extern __shared__ char smraw[];
    __nv_bfloat16* sbase = reinterpret_cast<__nv_bfloat16*>(smraw);
    float* sC = reinterpret_cast<float*>(smraw);

    int tid = threadIdx.x;
    int wid = tid >> 5;
    int wm = wid >> 1;        // 0..3 : M (o) slice of 32
    int wn = wid & 1;         // 0..1 : N (p) slice of 64
    int p0 = blockIdx.x * 128;
    int oB = blockIdx.y * 128;

    // stage tile loader: 16 cp.async x 16B per thread
    auto load_chunk = [&](int ch, int st) {
        __nv_bfloat16* s = sbase + st*STAGE_ELE;
        int k0 = ch * 64;
        #pragma unroll
        for (int it = 0; it < 4; it++) {
            int i = tid + it*256;            // 0..1023
            int row = i >> 3, q = i & 7;
            int off = row*TLD + q*8;
            cpasync16(s + off,              g_bhi + (size_t)(oB+row)*CC + k0 + q*8);
            cpasync16(s + TILE_ELE + off,   g_blo + (size_t)(oB+row)*CC + k0 + q*8);
            cpasync16(s + 2*TILE_ELE + off, g_ahi + (size_t)(p0+row)*CC + k0 + q*8);
            cpasync16(s + 3*TILE_ELE + off, g_alo + (size_t)(p0+row)*CC + k0 + q*8);
        }
        asm volatile("cp.async.commit_group;");
    };

    wmma::fragment<wmma::accumulator, 16,16,16, float> acc[2][4];
    #pragma unroll
    for (int m = 0; m < 2; m++)
        #pragma unroll
        for (int n = 0; n < 4; n++) wmma::fill_fragment(acc[m][n], 0.0f);

    load_chunk(0, 0);

    for (int ch = 0; ch < 4; ch++) {
        if (ch < 3) {
            load_chunk(ch+1, (ch+1) & 1);
            asm volatile("cp.async.wait_group 1;");
        } else {
            asm volatile("cp.async.wait_group 0;");
        }
        __syncthreads();

        __nv_bfloat16* s = sbase + (ch & 1)*STAGE_ELE;
        __nv_bfloat16* sAhi = s;
        __nv_bfloat16* sBhi = s + 2*TILE_ELE;

        #pragma unroll
        for (int ks = 0; ks < 4; ks++) {
            wmma::fragment<wmma::matrix_a, 16,16,16, __nv_bfloat16, wmma::row_major> ah[2], al[2];
            #pragma unroll
            for (int m = 0; m < 2; m++) {
                const __nv_bfloat16* ap = sAhi + (wm*32 + m*16)*TLD + ks*16;
                wmma::load_matrix_sync(ah[m], ap, TLD);
                wmma::load_matrix_sync(al[m], ap + TILE_ELE, TLD);    // Alo
            }
            #pragma unroll
            for (int n = 0; n < 4; n++) {
                wmma::fragment<wmma::matrix_b, 16,16,16, __nv_bfloat16, wmma::col_major> bh, bl;
                const __nv_bfloat16* bp = sBhi + (wn*64 + n*16)*TLD + ks*16;
                wmma::load_matrix_sync(bh, bp, TLD);
                wmma::load_matrix_sync(bl, bp + TILE_ELE, TLD);       // Blo
                #pragma unroll
                for (int m = 0; m < 2; m++) {
                    wmma::mma_sync(acc[m][n], ah[m], bh, acc[m][n]);
                    wmma::mma_sync(acc[m][n], al[m], bh, acc[m][n]);
                    wmma::mma_sync(acc[m][n], ah[m], bl, acc[m][n]);
                }
            }
        }
        __syncthreads();   // all warps done with this stage before its buffer is reloaded
    }

    // Epilogue: frags -> smem -> bias add -> coalesced g_vel[o][p]
    #pragma unroll
    for (int m = 0; m < 2; m++)
        #pragma unroll
        for (int n = 0; n < 4; n++)
            wmma::store_matrix_sync(sC + (wm*32 + m*16)*EPI_LD + wn*64 + n*16,
                                    acc[m][n], EPI_LD, wmma::mem_row_major);
    __syncthreads();
    for (int i = tid; i < 128*128; i += 256) {
        int c = i & 127, r = i >> 7;
        int p = p0 + c;
        if (p < HWSZ) {
            int o = oB + r;
            g_vel[(size_t)o*HWSZ + p] = sC[r*EPI_LD + c] + bv[o];
        }
    }
}

// ======================= transform + bicubic sample =======================
__device__ __forceinline__ float cc1f(float x) {
    return (1.25f*x - 2.25f)*x*x + 1.0f;
}
__device__ __forceinline__ float cc2f(float x) {
    return ((-0.75f*x + 3.75f)*x - 6.0f)*x + 3.0f;
}
// Small-angle sin/cos, |x| <~ 1: abs err < 3e-9 / 3e-10 — tighter than sincosf.
__device__ __forceinline__ void sincos_small(float x, float& s, float& c) {
    float x2 = x*x;
    s = x * fmaf(x2, fmaf(x2, fmaf(x2, -1.9841270e-4f, 8.3333333e-3f), -1.6666667e-1f), 1.0f);
    c = fmaf(x2, fmaf(x2, fmaf(x2, fmaf(x2, 2.4801587e-5f, -1.3888889e-3f), 4.1666667e-2f), -0.5f), 1.0f);
}

__global__ __launch_bounds__(256) void sample_kernel(const float* __restrict__ lat_grid,
                                                     const float* __restrict__ lon_grid,
                                                     const int*   __restrict__ dtp,
                                                     float* __restrict__ out) {
    int p = blockIdx.x * blockDim.x + threadIdx.x;
    if (p >= HWSZ) return;
    int c = blockIdx.y;

    int iv = *dtp;
    float dtf = (iv >= -1000000 && iv <= 1000000) ? (float)iv : __int_as_float(iv);

    float u = g_vel[c*HWSZ + p];
    float v = g_vel[(c + CC)*HWSZ + p];
    float2 sc = g_psc[p];
    float sP = sc.x, cP = sc.y;
    float lon_p = lon_grid[p];
    float min_lat = lat_grid[0], max_lat = lat_grid[(HH-1)*WW];
    float min_lon = lon_grid[0], max_lon = lon_grid[WW-1];

    float lon_pr = -u * dtf, lat_pr = -v * dtf;
    float slp, clp; sincos_small(lat_pr, slp, clp);
    float slo, clo; sincos_small(lon_pr, slo, clo);

    float sin_lat = slp*cP + clp*clo*sP;
    sin_lat = fminf(fmaxf(sin_lat, -1.0f + 1e-7f), 1.0f - 1e-7f);
    float lat_dep = asinf(sin_lat);

    float num = clp * slo;
    float den = clp*clo*cP - slp*sP;
    const float TWO_PI = 6.283185307179586f;
    float lon_dep = lon_p + atan2f(num, den) + TWO_PI;
    lon_dep = lon_dep - TWO_PI * floorf(lon_dep * (1.0f / TWO_PI));

    float gx = (2.0f*(lon_dep - min_lon)/(max_lon - min_lon) - 1.0f) * ((float)WW / (float)WP);
    float gy = (2.0f*(lat_dep - min_lat)/(max_lat - min_lat) - 1.0f) * ((float)HH / (float)HP);
    float g1 = gx + 1.0f;
    gx = g1 - 2.0f*floorf(g1*0.5f) - 1.0f;
    if (gy < -1.0f)     gy = -(2.0f + gy);
    else if (gy > 1.0f) gy = 2.0f - gy;

    float ix = (gx + 1.0f) * 0.5f * (float)(WP - 1);
    float iy = (gy + 1.0f) * 0.5f * (float)(HP - 1);
    float ix0f = floorf(ix), iy0f = floorf(iy);
    float tx = ix - ix0f, ty = iy - iy0f;
    int ix0 = (int)ix0f, iy0 = (int)iy0f;

    float wx0 = cc2f(tx + 1.0f), wx1 = cc1f(tx), wx2 = cc1f(1.0f - tx), wx3 = cc2f(2.0f - tx);
    float wy0 = cc2f(ty + 1.0f), wy1 = cc1f(ty), wy2 = cc1f(1.0f - ty), wy3 = cc2f(2.0f - ty);

    int x0 = min(max(ix0 - 1, 0), WP-1);
    int x1 = min(max(ix0    , 0), WP-1);
    int x2 = min(max(ix0 + 1, 0), WP-1);
    int x3 = min(max(ix0 + 2, 0), WP-1);

    const float* img = g_pad + c*HP*WP;
    float acc = 0.f;
    float wyv[4] = {wy0, wy1, wy2, wy3};
    #pragma unroll
    for (int i = 0; i < 4; i++) {
        int yi = min(max(iy0 + i - 1, 0), HP-1);
        const float* r = img + yi*WP;
        float rowv = wx0*r[x0] + wx1*r[x1] + wx2*r[x2] + wx3*r[x3];
        acc += wyv[i] * rowv;
    }
    out[c*HWSZ + p] = acc;
}

extern "C" void kernel_launch(void* const* d_in, const int* in_sizes, int n_in,
                              void* d_out, int out_size) {
    const float* hf   = (const float*)d_in[0];
    const float* latg = (const float*)d_in[1];
    const float* long_= (const float*)d_in[2];
    const float* wv   = (const float*)d_in[3];
    const float* bv   = (const float*)d_in[4];
    const int*   dtp  = (const int*)  d_in[5];
    float* out = (float*)d_out;

    cudaFuncSetAttribute(gemm_hmma, cudaFuncAttributeMaxDynamicSharedMemorySize, SM_BYTES);

    pad_kernel<<<(CC*HP*WP + 255)/256, 256>>>(hf);
    psc_kernel<<<(HWSZ + 255)/256, 256>>>(latg);

    convert_hf<<<dim3(PPAD/32, CC/64), dim3(32,8)>>>(hf);
    convert_w<<<(OO*CC + 255)/256, 256>>>(wv);

    gemm_hmma<<<dim3(507, OO/128), 256, SM_BYTES>>>(bv);

    dim3 gs((HWSZ + 255)/256, CC);
    sample_kernel<<<gs, 256>>>(latg, long_, dtp, out);
}

// round 14
// speedup vs baseline: 1.8627x; 1.1491x over previous
#include <cuda_runtime.h>
#include <cuda_bf16.h>
#include <mma.h>
#include <cstdint>

using namespace nvcuda;

#define CC   256
#define HH   180
#define WW   360
#define HWSZ (HH*WW)          // 64800
#define HP   (HH+2)           // 182
#define WP   (WW+2)           // 362
#define OO   (2*CC)           // 512
#define PPAD 64896            // 507*128 pixel rows (padded)

// Scratch (no cudaMalloc allowed)
__device__ float g_vel[OO*HWSZ];             // velocity field [o][p]
__device__ float2 g_psc[HWSZ];               // per-pixel {sin(lat_p), cos(lat_p)}
__device__ __nv_bfloat16 g_ahi[PPAD*CC];     // hidden transposed [p][c], hi part
__device__ __nv_bfloat16 g_alo[PPAD*CC];     // lo part
__device__ __nv_bfloat16 g_bhi[OO*CC];       // weights [o][c] hi
__device__ __nv_bfloat16 g_blo[OO*CC];       // weights lo

// ======================= per-pixel sincos(lat) precompute =======================
__global__ void psc_kernel(const float* __restrict__ lat_grid) {
    int p = blockIdx.x * blockDim.x + threadIdx.x;
    if (p >= HWSZ) return;
    float s, c;
    sincosf(lat_grid[p], &s, &c);
    g_psc[p] = make_float2(s, c);
}

// ======================= convert: hf [C][P] fp32 -> [P][C] bf16 hi/lo =======================
__global__ __launch_bounds__(256) void convert_hf(const float* __restrict__ hf) {
    __shared__ float tile[64][33];
    int p0 = blockIdx.x * 32;
    int c0 = blockIdx.y * 64;
    int tx = threadIdx.x, ty = threadIdx.y;
    #pragma unroll
    for (int i = 0; i < 8; i++) {
        int c = c0 + ty + i*8;
        int p = p0 + tx;
        tile[ty + i*8][tx] = (p < HWSZ) ? hf[(size_t)c*HWSZ + p] : 0.f;
    }
    __syncthreads();
    #pragma unroll
    for (int i = 0; i < 4; i++) {
        int pl = ty + i*8;
        int p  = p0 + pl;
        float v0 = tile[2*tx][pl];
        float v1 = tile[2*tx+1][pl];
        __nv_bfloat16 h0 = __float2bfloat16(v0);
        __nv_bfloat16 h1 = __float2bfloat16(v1);
        __nv_bfloat16 l0 = __float2bfloat16(v0 - __bfloat162float(h0));
        __nv_bfloat16 l1 = __float2bfloat16(v1 - __bfloat162float(h1));
        size_t o = (size_t)p*CC + c0 + 2*tx;
        *reinterpret_cast<__nv_bfloat162*>(g_ahi + o) = __nv_bfloat162(h0, h1);
        *reinterpret_cast<__nv_bfloat162*>(g_alo + o) = __nv_bfloat162(l0, l1);
    }
}

__global__ void convert_w(const float* __restrict__ wv) {
    int i = blockIdx.x * blockDim.x + threadIdx.x;
    if (i >= OO*CC) return;
    float v = wv[i];
    __nv_bfloat16 h = __float2bfloat16(v);
    g_bhi[i] = h;
    g_blo[i] = __float2bfloat16(v - __bfloat162float(h));
}

// ======================= HMMA (wmma) GEMM, 2-stage cp.async, 2 CTAs/SM ================
// vel[o][p] = sum_c w[o][c]*hf[c][p] + b[o]
// A = w [o][c] row-major (g_bhi/g_blo), B = hf^T [p][c] -> wmma col_major (g_ahi/g_alo)
// CTA tile: M=128 (o) x N=128 (p), K chunks of 32 (8 chunks). 8 warps = 4(M) x 2(N).
// hi/lo split: acc += Ahi*Bhi + Alo*Bhi + Ahi*Blo (fp32 accumulate).
#define KC    32
#define TLD   40                       // smem tile ld: 32 elems + 8 skew (80B rows)
#define TILE_ELE (128*TLD)             // 5120 bf16 per tile (10240 B)
#define STAGE_ELE (4*TILE_ELE)         // Ahi,Alo,Bhi,Blo = 40960 B
#define EPI_LD 132
#define SM_BYTES (2*STAGE_ELE*2)       // 81920 B; epilogue 128*132*4=67584 fits

__device__ __forceinline__ void cpasync16(void* smem_dst, const void* gsrc) {
    uint32_t d = (uint32_t)__cvta_generic_to_shared(smem_dst);
    asm volatile("cp.async.cg.shared.global [%0], [%1], 16;" :: "r"(d), "l"(gsrc));
}

__global__ __launch_bounds__(256, 2) void gemm_hmma(const float* __restrict__ bv) {
    extern __shared__ char smraw[];
    __nv_bfloat16* sbase = reinterpret_cast<__nv_bfloat16*>(smraw);
    float* sC = reinterpret_cast<float*>(smraw);

    int tid = threadIdx.x;
    int wid = tid >> 5;
    int wm = wid >> 1;        // 0..3 : M (o) slice of 32
    int wn = wid & 1;         // 0..1 : N (p) slice of 64
    int p0 = blockIdx.x * 128;
    int oB = blockIdx.y * 128;

    // stage tile loader: 8 cp.async x 16B per thread
    auto load_chunk = [&](int ch, int st) {
        __nv_bfloat16* s = sbase + st*STAGE_ELE;
        int k0 = ch * KC;
        #pragma unroll
        for (int it = 0; it < 2; it++) {
            int i = tid + it*256;            // 0..511
            int row = i >> 2, q = i & 3;     // row 0..127, q = 16B slot within 64B row
            int off = row*TLD + q*8;
            size_t ga = (size_t)(oB+row)*CC + k0 + q*8;
            size_t gb = (size_t)(p0+row)*CC + k0 + q*8;
            cpasync16(s + off,              g_bhi + ga);
            cpasync16(s + TILE_ELE + off,   g_blo + ga);
            cpasync16(s + 2*TILE_ELE + off, g_ahi + gb);
            cpasync16(s + 3*TILE_ELE + off, g_alo + gb);
        }
        asm volatile("cp.async.commit_group;");
    };

    wmma::fragment<wmma::accumulator, 16,16,16, float> acc[2][4];
    #pragma unroll
    for (int m = 0; m < 2; m++)
        #pragma unroll
        for (int n = 0; n < 4; n++) wmma::fill_fragment(acc[m][n], 0.0f);

    load_chunk(0, 0);

    for (int ch = 0; ch < 8; ch++) {
        if (ch < 7) {
            load_chunk(ch+1, (ch+1) & 1);
            asm volatile("cp.async.wait_group 1;");
        } else {
            asm volatile("cp.async.wait_group 0;");
        }
        __syncthreads();

        __nv_bfloat16* s = sbase + (ch & 1)*STAGE_ELE;
        __nv_bfloat16* sAhi = s;
        __nv_bfloat16* sBhi = s + 2*TILE_ELE;

        #pragma unroll
        for (int ks = 0; ks < 2; ks++) {
            wmma::fragment<wmma::matrix_a, 16,16,16, __nv_bfloat16, wmma::row_major> ah[2], al[2];
            #pragma unroll
            for (int m = 0; m < 2; m++) {
                const __nv_bfloat16* ap = sAhi + (wm*32 + m*16)*TLD + ks*16;
                wmma::load_matrix_sync(ah[m], ap, TLD);
                wmma::load_matrix_sync(al[m], ap + TILE_ELE, TLD);    // Alo
            }
            #pragma unroll
            for (int n = 0; n < 4; n++) {
                wmma::fragment<wmma::matrix_b, 16,16,16, __nv_bfloat16, wmma::col_major> bh, bl;
                const __nv_bfloat16* bp = sBhi + (wn*64 + n*16)*TLD + ks*16;
                wmma::load_matrix_sync(bh, bp, TLD);
                wmma::load_matrix_sync(bl, bp + TILE_ELE, TLD);       // Blo
                #pragma unroll
                for (int m = 0; m < 2; m++) {
                    wmma::mma_sync(acc[m][n], ah[m], bh, acc[m][n]);
                    wmma::mma_sync(acc[m][n], al[m], bh, acc[m][n]);
                    wmma::mma_sync(acc[m][n], ah[m], bl, acc[m][n]);
                }
            }
        }
        __syncthreads();   // stage buffer free before next reload
    }

    // Epilogue: frags -> smem -> bias add -> coalesced g_vel[o][p]
    #pragma unroll
    for (int m = 0; m < 2; m++)
        #pragma unroll
        for (int n = 0; n < 4; n++)
            wmma::store_matrix_sync(sC + (wm*32 + m*16)*EPI_LD + wn*64 + n*16,
                                    acc[m][n], EPI_LD, wmma::mem_row_major);
    __syncthreads();
    for (int i = tid; i < 128*128; i += 256) {
        int c = i & 127, r = i >> 7;
        int p = p0 + c;
        if (p < HWSZ) {
            int o = oB + r;
            g_vel[(size_t)o*HWSZ + p] = sC[r*EPI_LD + c] + bv[o];
        }
    }
}

// ======================= transform + bicubic sample (pad fused inline) ===============
__device__ __forceinline__ float cc1f(float x) {
    return (1.25f*x - 2.25f)*x*x + 1.0f;
}
__device__ __forceinline__ float cc2f(float x) {
    return ((-0.75f*x + 3.75f)*x - 6.0f)*x + 3.0f;
}
// Small-angle sin/cos, |x| <~ 1: abs err < 3e-9 / 3e-10 — tighter than sincosf.
__device__ __forceinline__ void sincos_small(float x, float& s, float& c) {
    float x2 = x*x;
    s = x * fmaf(x2, fmaf(x2, fmaf(x2, -1.9841270e-4f, 8.3333333e-3f), -1.6666667e-1f), 1.0f);
    c = fmaf(x2, fmaf(x2, fmaf(x2, fmaf(x2, 2.4801587e-5f, -1.3888889e-3f), 4.1666667e-2f), -0.5f), 1.0f);
}

__global__ __launch_bounds__(256) void sample_kernel(const float* __restrict__ hf,
                                                     const float* __restrict__ lat_grid,
                                                     const float* __restrict__ lon_grid,
                                                     const int*   __restrict__ dtp,
                                                     float* __restrict__ out) {
    int p = blockIdx.x * blockDim.x + threadIdx.x;
    if (p >= HWSZ) return;
    int c = blockIdx.y;

    int iv = *dtp;
    float dtf = (iv >= -1000000 && iv <= 1000000) ? (float)iv : __int_as_float(iv);

    float u = g_vel[c*HWSZ + p];
    float v = g_vel[(c + CC)*HWSZ + p];
    float2 sc = g_psc[p];
    float sP = sc.x, cP = sc.y;
    float lon_p = lon_grid[p];
    float min_lat = lat_grid[0], max_lat = lat_grid[(HH-1)*WW];
    float min_lon = lon_grid[0], max_lon = lon_grid[WW-1];

    float lon_pr = -u * dtf, lat_pr = -v * dtf;
    float slp, clp; sincos_small(lat_pr, slp, clp);
    float slo, clo; sincos_small(lon_pr, slo, clo);

    float sin_lat = slp*cP + clp*clo*sP;
    sin_lat = fminf(fmaxf(sin_lat, -1.0f + 1e-7f), 1.0f - 1e-7f);
    float lat_dep = asinf(sin_lat);

    float num = clp * slo;
    float den = clp*clo*cP - slp*sP;
    const float TWO_PI = 6.283185307179586f;
    float lon_dep = lon_p + atan2f(num, den) + TWO_PI;
    lon_dep = lon_dep - TWO_PI * floorf(lon_dep * (1.0f / TWO_PI));

    float gx = (2.0f*(lon_dep - min_lon)/(max_lon - min_lon) - 1.0f) * ((float)WW / (float)WP);
    float gy = (2.0f*(lat_dep - min_lat)/(max_lat - min_lat) - 1.0f) * ((float)HH / (float)HP);
    float g1 = gx + 1.0f;
    gx = g1 - 2.0f*floorf(g1*0.5f) - 1.0f;
    if (gy < -1.0f)     gy = -(2.0f + gy);
    else if (gy > 1.0f) gy = 2.0f - gy;

    float ix = (gx + 1.0f) * 0.5f * (float)(WP - 1);
    float iy = (gy + 1.0f) * 0.5f * (float)(HP - 1);
    float ix0f = floorf(ix), iy0f = floorf(iy);
    float tx = ix - ix0f, ty = iy - iy0f;
    int ix0 = (int)ix0f, iy0 = (int)iy0f;

    float wx0 = cc2f(tx + 1.0f), wx1 = cc1f(tx), wx2 = cc1f(1.0f - tx), wx3 = cc2f(2.0f - tx);
    float wy0 = cc2f(ty + 1.0f), wy1 = cc1f(ty), wy2 = cc1f(1.0f - ty), wy3 = cc2f(2.0f - ty);

    // padded-space x taps -> source x indices (normal + pole-rolled variants)
    int xn[4], xr[4];
    #pragma unroll
    for (int j = 0; j < 4; j++) {
        int xp = min(max(ix0 + j - 1, 0), WP-1);
        int x = xp - 1;
        if (x < 0)   x += WW;
        if (x >= WW) x -= WW;
        xn[j] = x;
        int x2 = x - WW/2;
        if (x2 < 0) x2 += WW;
        xr[j] = x2;
    }

    const float* img = hf + (size_t)c*HWSZ;
    float acc = 0.f;
    float wyv[4] = {wy0, wy1, wy2, wy3};
    #pragma unroll
    for (int i = 0; i < 4; i++) {
        int yp = min(max(iy0 + i - 1, 0), HP-1);
        int yy; bool roll;
        if (yp == 0)         { yy = 0;      roll = true; }
        else if (yp == HP-1) { yy = HH-1;   roll = true; }
        else                 { yy = yp - 1; roll = false; }
        const float* r = img + yy*WW;
        float rowv;
        if (roll) rowv = wx0*r[xr[0]] + wx1*r[xr[1]] + wx2*r[xr[2]] + wx3*r[xr[3]];
        else      rowv = wx0*r[xn[0]] + wx1*r[xn[1]] + wx2*r[xn[2]] + wx3*r[xn[3]];
        acc += wyv[i] * rowv;
    }
    out[c*HWSZ + p] = acc;
}

extern "C" void kernel_launch(void* const* d_in, const int* in_sizes, int n_in,
                              void* d_out, int out_size) {
    const float* hf   = (const float*)d_in[0];
    const float* latg = (const float*)d_in[1];
    const float* long_= (const float*)d_in[2];
    const float* wv   = (const float*)d_in[3];
    const float* bv   = (const float*)d_in[4];
    const int*   dtp  = (const int*)  d_in[5];
    float* out = (float*)d_out;

    cudaFuncSetAttribute(gemm_hmma, cudaFuncAttributeMaxDynamicSharedMemorySize, SM_BYTES);

    psc_kernel<<<(HWSZ + 255)/256, 256>>>(latg);
    convert_hf<<<dim3(PPAD/32, CC/64), dim3(32,8)>>>(hf);
    convert_w<<<(OO*CC + 255)/256, 256>>>(wv);

    gemm_hmma<<<dim3(507, OO/128), 256, SM_BYTES>>>(bv);

    dim3 gs((HWSZ + 255)/256, CC);
    sample_kernel<<<gs, 256>>>(hf, latg, long_, dtp, out);
}